// round 2
// baseline (speedup 1.0000x reference)
#include <cuda_runtime.h>
#include <cuda_bf16.h>
#include <math.h>

// ---------------------------------------------------------------------------
// Problem constants
// ---------------------------------------------------------------------------
#define S_LEN   8192
#define HID     2048
#define NH      16
#define HD      128           // head dim
#define BLK     256           // chunk length
#define NC      32            // S/BLK
#define HDTOT   2048          // NH*HD
#define QKV_N   6144          // 3*NH*HD
#define EPS     1e-5f
#define SCALE_Q 0.08838834764831845f   // 128^-0.5

// ---------------------------------------------------------------------------
// Scratch (static device globals; no allocation allowed)
// ---------------------------------------------------------------------------
__device__ float d_qkv [ (size_t)S_LEN * QKV_N ];     // 201 MB; q,k overwritten in place
__device__ float d_attn[ (size_t)S_LEN * HDTOT ];     // 67 MB
__device__ float d_g   [ (size_t)S_LEN * HDTOT ];     // 67 MB (gate, then y in place)
__device__ float d_kvc [ (size_t)NC * NH * HD * HD ]; // 33.5 MB per-chunk KV contributions
__device__ float d_kvs [ (size_t)NC * NH * HD * HD ]; // 33.5 MB prefix KV states

__device__ float c_invfreq[64];
__device__ float c_slopes[16];

// ---------------------------------------------------------------------------
// Tables: RoPE inv_freq (double precision), ALiBi-style slopes
// ---------------------------------------------------------------------------
__global__ void init_tables_kernel() {
    int t = threadIdx.x;
    if (t < 64) {
        double e = ((double)(2 * t) / 128.0) * log(600000.0);
        c_invfreq[t] = (float)exp(-e);
    }
    if (t < 16) {
        // start = 2^(-2^(-(log2(16)-3))) = 2^-0.5 ; slopes[i] = start^(i+1)
        double s = exp2(-0.5 * (double)(t + 1));
        c_slopes[t] = (float)(s * (1.0 - 0.0 / 19.0 + 1e-5));
    }
}

// ---------------------------------------------------------------------------
// SGEMM (TN): C[M,N] = A[M,K] * B[N,K]^T (+ bias[N])
// 128x128 tile, BK=16, 256 threads, 8x8 microtile.
// All dims are multiples of 128/16 in this problem; no bounds checks.
// ---------------------------------------------------------------------------
template <bool HAS_BIAS>
__global__ __launch_bounds__(256)
void sgemm_tn(const float* __restrict__ A, const float* __restrict__ B,
              const float* __restrict__ bias, float* __restrict__ C,
              int M, int N, int K)
{
    __shared__ float As[16][132];
    __shared__ float Bs[16][132];

    const int tid  = threadIdx.x;
    const int row0 = blockIdx.y * 128;
    const int col0 = blockIdx.x * 128;
    const int tx   = tid & 15;
    const int ty   = tid >> 4;

    float acc[8][8];
#pragma unroll
    for (int i = 0; i < 8; i++)
#pragma unroll
        for (int j = 0; j < 8; j++) acc[i][j] = 0.f;

    for (int k0 = 0; k0 < K; k0 += 16) {
#pragma unroll
        for (int l = 0; l < 2; l++) {
            int idx = tid + l * 256;
            int r   = idx >> 2;          // 0..127
            int kq  = (idx & 3) * 4;     // 0,4,8,12
            float4 va = *(const float4*)&A[(size_t)(row0 + r) * K + k0 + kq];
            As[kq + 0][r] = va.x; As[kq + 1][r] = va.y;
            As[kq + 2][r] = va.z; As[kq + 3][r] = va.w;
            float4 vb = *(const float4*)&B[(size_t)(col0 + r) * K + k0 + kq];
            Bs[kq + 0][r] = vb.x; Bs[kq + 1][r] = vb.y;
            Bs[kq + 2][r] = vb.z; Bs[kq + 3][r] = vb.w;
        }
        __syncthreads();

#pragma unroll
        for (int kk = 0; kk < 16; kk++) {
            float a[8], b[8];
            *(float4*)&a[0] = *(const float4*)&As[kk][ty * 8];
            *(float4*)&a[4] = *(const float4*)&As[kk][ty * 8 + 4];
            *(float4*)&b[0] = *(const float4*)&Bs[kk][tx * 8];
            *(float4*)&b[4] = *(const float4*)&Bs[kk][tx * 8 + 4];
#pragma unroll
            for (int i = 0; i < 8; i++)
#pragma unroll
                for (int j = 0; j < 8; j++)
                    acc[i][j] += a[i] * b[j];
        }
        __syncthreads();
    }

    float bb[8];
#pragma unroll
    for (int j = 0; j < 8; j++)
        bb[j] = HAS_BIAS ? bias[col0 + tx * 8 + j] : 0.f;

#pragma unroll
    for (int i = 0; i < 8; i++) {
        size_t base = (size_t)(row0 + ty * 8 + i) * N + col0 + tx * 8;
        float4 o0, o1;
        o0.x = acc[i][0] + bb[0]; o0.y = acc[i][1] + bb[1];
        o0.z = acc[i][2] + bb[2]; o0.w = acc[i][3] + bb[3];
        o1.x = acc[i][4] + bb[4]; o1.y = acc[i][5] + bb[5];
        o1.z = acc[i][6] + bb[6]; o1.w = acc[i][7] + bb[7];
        *(float4*)&C[base]     = o0;
        *(float4*)&C[base + 4] = o1;
    }
}

// ---------------------------------------------------------------------------
// Per-head RMSNorm + RoPE + q-scale, in place on d_qkv.
// grid (S, NH), 128 threads (one per head-dim element).
// ---------------------------------------------------------------------------
__global__ __launch_bounds__(128)
void normrope_kernel(const int* __restrict__ positions,
                     const float* __restrict__ qw,
                     const float* __restrict__ kw)
{
    int s = blockIdx.x;
    int h = blockIdx.y;
    int d = threadIdx.x;
    int lane = d & 31;
    int wrp  = d >> 5;

    size_t qoff = (size_t)s * QKV_N + h * HD + d;
    size_t koff = qoff + HDTOT;
    float qv = d_qkv[qoff];
    float kv = d_qkv[koff];

    float sq = qv * qv, sk = kv * kv;
#pragma unroll
    for (int off = 16; off > 0; off >>= 1) {
        sq += __shfl_xor_sync(0xffffffffu, sq, off);
        sk += __shfl_xor_sync(0xffffffffu, sk, off);
    }
    __shared__ float redq[4], redk[4];
    if (lane == 0) { redq[wrp] = sq; redk[wrp] = sk; }
    __syncthreads();
    float msq = (redq[0] + redq[1] + redq[2] + redq[3]) * (1.f / 128.f);
    float msk = (redk[0] + redk[1] + redk[2] + redk[3]) * (1.f / 128.f);

    float qn = qv * rsqrtf(msq + EPS) * qw[d];
    float kn = kv * rsqrtf(msk + EPS) * kw[d];

    __shared__ float qs[128], ks[128];
    qs[d] = qn; ks[d] = kn;
    __syncthreads();

    int i = d & 63;
    float ang = (float)positions[s] * c_invfreq[i];
    float sn, cs;
    sincosf(ang, &sn, &cs);

    float q1 = qs[i], q2 = qs[i + 64];
    float k1 = ks[i], k2 = ks[i + 64];
    float oq = (d < 64) ? (q1 * cs - q2 * sn) : (q2 * cs + q1 * sn);
    float ok = (d < 64) ? (k1 * cs - k2 * sn) : (k2 * cs + k1 * sn);

    d_qkv[qoff] = oq * SCALE_Q;
    d_qkv[koff] = ok;
}

// ---------------------------------------------------------------------------
// Phase 1: per-chunk KV contribution  KV[c,h,d,e] = sum_j kdecay[j]*k[j,d]*v[j,e]
// grid (NC, NH), 256 threads, 128x128 output, 8x8 microtile, j-tiles of 32.
// ---------------------------------------------------------------------------
__global__ __launch_bounds__(256)
void chunk_kv_kernel()
{
    __shared__ float ks[32][128];
    __shared__ float vs[32][128];

    int c = blockIdx.x, h = blockIdx.y;
    int tid = threadIdx.x;
    int tx = tid & 15, ty = tid >> 4;
    float slope = c_slopes[h];

    float acc[8][8];
#pragma unroll
    for (int i = 0; i < 8; i++)
#pragma unroll
        for (int j = 0; j < 8; j++) acc[i][j] = 0.f;

    for (int jt = 0; jt < BLK; jt += 32) {
#pragma unroll
        for (int l = 0; l < 4; l++) {
            int idx = tid + l * 256;       // 0..1023 float4 slots
            int r   = idx >> 5;            // 0..31
            int dq  = (idx & 31) * 4;
            int tok = c * BLK + jt + r;
            float kd = expf(-slope * (float)(BLK - 1 - (jt + r)));
            size_t kb = (size_t)tok * QKV_N + HDTOT + h * HD + dq;
            size_t vb = (size_t)tok * QKV_N + 2 * HDTOT + h * HD + dq;
            float4 kvv = *(const float4*)&d_qkv[kb];
            float4 vvv = *(const float4*)&d_qkv[vb];
            ks[r][dq + 0] = kvv.x * kd; ks[r][dq + 1] = kvv.y * kd;
            ks[r][dq + 2] = kvv.z * kd; ks[r][dq + 3] = kvv.w * kd;
            *(float4*)&vs[r][dq] = vvv;
        }
        __syncthreads();

#pragma unroll 8
        for (int jj = 0; jj < 32; jj++) {
            float a[8], b[8];
            *(float4*)&a[0] = *(const float4*)&ks[jj][ty * 8];
            *(float4*)&a[4] = *(const float4*)&ks[jj][ty * 8 + 4];
            *(float4*)&b[0] = *(const float4*)&vs[jj][tx * 8];
            *(float4*)&b[4] = *(const float4*)&vs[jj][tx * 8 + 4];
#pragma unroll
            for (int i = 0; i < 8; i++)
#pragma unroll
                for (int j = 0; j < 8; j++)
                    acc[i][j] += a[i] * b[j];
        }
        __syncthreads();
    }

    size_t base = ((size_t)(c * NH + h) * HD) * HD;
#pragma unroll
    for (int i = 0; i < 8; i++) {
        size_t o = base + (size_t)(ty * 8 + i) * HD + tx * 8;
        *(float4*)&d_kvc[o]     = *(float4*)&acc[i][0];
        *(float4*)&d_kvc[o + 4] = *(float4*)&acc[i][4];
    }
}

// ---------------------------------------------------------------------------
// Phase 1b: sequential scan over chunks (per element):
//   kvs[c] = state before chunk c ; state = blk_decay*state + kvc[c]
// ---------------------------------------------------------------------------
__global__ __launch_bounds__(256)
void kv_scan_kernel()
{
    int p  = blockIdx.x * 256 + threadIdx.x;   // 0 .. NH*HD*HD-1
    int h  = p >> 14;
    int de = p & 16383;
    float bd = expf(-c_slopes[h] * (float)BLK);
    float st = 0.f;
#pragma unroll 1
    for (int c = 0; c < NC; c++) {
        size_t o = (((size_t)(c * NH + h)) << 14) + de;
        d_kvs[o] = st;
        st = bd * st + d_kvc[o];
    }
}

// ---------------------------------------------------------------------------
// Phase 2: intra (masked, decayed) + inter attention.
// grid (4, NC, NH): each block handles 64 query rows of one (chunk, head).
// Dynamic smem layout:
//   qT[128][68], kT[128][68], v[64][128] (reused as kv tile [32][128]),
//   sT[64][68], tbl[256]
// ---------------------------------------------------------------------------
#define ATTN_SMEM_FLOATS (128*68 + 128*68 + 64*128 + 64*68 + 256)

__global__ __launch_bounds__(256)
void attn_block_kernel()
{
    extern __shared__ float sm[];
    float* qT  = sm;                    // [128][68]
    float* kT  = qT + 128 * 68;         // [128][68]
    float* vS  = kT + 128 * 68;         // [64][128]  (also kv tile [32][128])
    float* sT  = vS + 64 * 128;         // [64][68]
    float* tbl = sT + 64 * 68;          // [256]

    const int rb  = blockIdx.x;         // row block (0..3)
    const int c   = blockIdx.y;
    const int h   = blockIdx.z;
    const int tid = threadIdx.x;
    const float slope = c_slopes[h];

    if (tid < 256) tbl[tid] = expf(-slope * (float)tid);

    const int s0 = c * BLK + rb * 64;   // first query token of this block

    // load q rows (already normed/roped/scaled) transposed into qT
#pragma unroll
    for (int l = 0; l < 8; l++) {
        int idx = tid + l * 256;        // 2048 float4 slots
        int r   = idx >> 5;             // 0..63
        int dq  = (idx & 31) * 4;
        float4 v = *(const float4*)&d_qkv[(size_t)(s0 + r) * QKV_N + h * HD + dq];
        qT[(dq + 0) * 68 + r] = v.x; qT[(dq + 1) * 68 + r] = v.y;
        qT[(dq + 2) * 68 + r] = v.z; qT[(dq + 3) * 68 + r] = v.w;
    }

    const int txS = tid & 15,  tyS = tid >> 4;
    const int i0  = tyS * 4;            // score rows    (also PV rows)
    const int j0  = txS * 4;            // score cols
    const int e0  = txS * 8;            // output cols

    float acc[4][8];
#pragma unroll
    for (int i = 0; i < 4; i++)
#pragma unroll
        for (int j = 0; j < 8; j++) acc[i][j] = 0.f;

    for (int jt = 0; jt <= rb; jt++) {
        __syncthreads();   // protect kT/vS/sT reuse and qT/tbl readiness
        // load k tile transposed, v tile straight
        int t0 = c * BLK + jt * 64;
#pragma unroll
        for (int l = 0; l < 8; l++) {
            int idx = tid + l * 256;
            int r   = idx >> 5;
            int dq  = (idx & 31) * 4;
            float4 kv = *(const float4*)&d_qkv[(size_t)(t0 + r) * QKV_N + HDTOT + h * HD + dq];
            kT[(dq + 0) * 68 + r] = kv.x; kT[(dq + 1) * 68 + r] = kv.y;
            kT[(dq + 2) * 68 + r] = kv.z; kT[(dq + 3) * 68 + r] = kv.w;
            float4 vv = *(const float4*)&d_qkv[(size_t)(t0 + r) * QKV_N + 2 * HDTOT + h * HD + dq];
            *(float4*)&vS[r * 128 + dq] = vv;
        }
        __syncthreads();

        // scores: s[i,j] = q_i . k_j   (64x64, K=128)
        float accS[4][4];
#pragma unroll
        for (int i = 0; i < 4; i++)
#pragma unroll
            for (int j = 0; j < 4; j++) accS[i][j] = 0.f;

#pragma unroll 4
        for (int dd = 0; dd < 128; dd++) {
            float a[4], b[4];
            *(float4*)a = *(const float4*)&qT[dd * 68 + i0];
            *(float4*)b = *(const float4*)&kT[dd * 68 + j0];
#pragma unroll
            for (int i = 0; i < 4; i++)
#pragma unroll
                for (int j = 0; j < 4; j++)
                    accS[i][j] += a[i] * b[j];
        }

        // mask + decay, write transposed sT[j][i]
#pragma unroll
        for (int i = 0; i < 4; i++) {
#pragma unroll
            for (int j = 0; j < 4; j++) {
                int dif = (rb * 64 + i0 + i) - (jt * 64 + j0 + j);
                float vsc = (dif >= 0) ? accS[i][j] * tbl[dif] : 0.f;
                sT[(j0 + j) * 68 + (i0 + i)] = vsc;
            }
        }
        __syncthreads();

        // out += sT^T @ v   (64x128, K=64)
#pragma unroll 4
        for (int jj = 0; jj < 64; jj++) {
            float a[4], b[8];
            *(float4*)a     = *(const float4*)&sT[jj * 68 + i0];
            *(float4*)&b[0] = *(const float4*)&vS[jj * 128 + e0];
            *(float4*)&b[4] = *(const float4*)&vS[jj * 128 + e0 + 4];
#pragma unroll
            for (int i = 0; i < 4; i++)
#pragma unroll
                for (int j = 0; j < 8; j++)
                    acc[i][j] += a[i] * b[j];
        }
    }

    // inter: out[i,e] += qdecay[i] * sum_d q[i,d] * kvs[c,h,d,e]
    float qd[4];
#pragma unroll
    for (int i = 0; i < 4; i++)
        qd[i] = expf(-slope * (float)(rb * 64 + i0 + i + 1));

    size_t kvbase = (((size_t)(c * NH + h)) << 14);
    for (int dt = 0; dt < 4; dt++) {
        __syncthreads();
#pragma unroll
        for (int l = 0; l < 4; l++) {
            int idx = tid + l * 256;      // 1024 float4 slots
            int r   = idx >> 5;           // 0..31
            int dq  = (idx & 31) * 4;
            *(float4*)&vS[r * 128 + dq] =
                *(const float4*)&d_kvs[kvbase + (size_t)(dt * 32 + r) * HD + dq];
        }
        __syncthreads();

#pragma unroll 4
        for (int dd = 0; dd < 32; dd++) {
            float a[4], b[8];
            *(float4*)a = *(const float4*)&qT[(dt * 32 + dd) * 68 + i0];
#pragma unroll
            for (int i = 0; i < 4; i++) a[i] *= qd[i];
            *(float4*)&b[0] = *(const float4*)&vS[dd * 128 + e0];
            *(float4*)&b[4] = *(const float4*)&vS[dd * 128 + e0 + 4];
#pragma unroll
            for (int i = 0; i < 4; i++)
#pragma unroll
                for (int j = 0; j < 8; j++)
                    acc[i][j] += a[i] * b[j];
        }
    }

    // write output rows to d_attn[s, h*128 + e]
#pragma unroll
    for (int i = 0; i < 4; i++) {
        size_t base = (size_t)(s0 + i0 + i) * HDTOT + h * HD + e0;
        *(float4*)&d_attn[base]     = *(float4*)&acc[i][0];
        *(float4*)&d_attn[base + 4] = *(float4*)&acc[i][4];
    }
}

// ---------------------------------------------------------------------------
// Group-RMSNorm (8 groups of 256) + sigmoid gating; y written over d_g.
// grid S, 256 threads; warp w == group w (32 lanes * 8 cols = 256 cols).
// ---------------------------------------------------------------------------
__global__ __launch_bounds__(256)
void gate_kernel(const float* __restrict__ gnw)
{
    int s = blockIdx.x;
    int t = threadIdx.x;
    size_t base = (size_t)s * HDTOT + t * 8;

    float a[8];
    *(float4*)&a[0] = *(const float4*)&d_attn[base];
    *(float4*)&a[4] = *(const float4*)&d_attn[base + 4];

    float ss = 0.f;
#pragma unroll
    for (int j = 0; j < 8; j++) ss += a[j] * a[j];
#pragma unroll
    for (int off = 16; off > 0; off >>= 1)
        ss += __shfl_xor_sync(0xffffffffu, ss, off);
    float rstd = rsqrtf(ss * (1.f / 256.f) + EPS);

    float g[8];
    *(float4*)&g[0] = *(const float4*)&d_g[base];
    *(float4*)&g[4] = *(const float4*)&d_g[base + 4];

    float y[8];
#pragma unroll
    for (int j = 0; j < 8; j++) {
        float sig = 1.f / (1.f + expf(-g[j]));
        y[j] = a[j] * rstd * gnw[t * 8 + j] * sig;
    }
    *(float4*)&d_g[base]     = *(float4*)&y[0];
    *(float4*)&d_g[base + 4] = *(float4*)&y[4];
}

// ---------------------------------------------------------------------------
// Launch
// ---------------------------------------------------------------------------
extern "C" void kernel_launch(void* const* d_in, const int* in_sizes, int n_in,
                              void* d_out, int out_size)
{
    const float* hs     = (const float*)d_in[0];
    const int*   pos    = (const int*)  d_in[1];
    const float* qkv_w  = (const float*)d_in[2];
    const float* qkv_b  = (const float*)d_in[3];
    const float* qnw    = (const float*)d_in[4];
    const float* knw    = (const float*)d_in[5];
    const float* g_w    = (const float*)d_in[6];
    const float* gnw    = (const float*)d_in[7];
    const float* dens_w = (const float*)d_in[8];
    float* out = (float*)d_out;

    // resolve device-global scratch pointers (no allocation)
    float *p_qkv, *p_g;
    cudaGetSymbolAddress((void**)&p_qkv, d_qkv);
    cudaGetSymbolAddress((void**)&p_g,   d_g);

    static_assert(ATTN_SMEM_FLOATS * 4 < 227 * 1024, "smem");
    cudaFuncSetAttribute(attn_block_kernel,
                         cudaFuncAttributeMaxDynamicSharedMemorySize,
                         ATTN_SMEM_FLOATS * 4);

    init_tables_kernel<<<1, 64>>>();

    // qkv = hs @ qkv_w^T + b
    sgemm_tn<true><<<dim3(QKV_N / 128, S_LEN / 128), 256>>>(
        hs, qkv_w, qkv_b, p_qkv, S_LEN, QKV_N, HID);

    // g = hs @ g_w^T  (independent of attention path; issued early)
    sgemm_tn<false><<<dim3(HDTOT / 128, S_LEN / 128), 256>>>(
        hs, g_w, nullptr, p_g, S_LEN, HDTOT, HID);

    // per-head rmsnorm + rope + q scale (in place)
    normrope_kernel<<<dim3(S_LEN, NH), 128>>>(pos, qnw, knw);

    // lightning attention
    chunk_kv_kernel<<<dim3(NC, NH), 256>>>();
    kv_scan_kernel<<<(NH * HD * HD) / 256, 256>>>();
    attn_block_kernel<<<dim3(4, NC, NH), 256, ATTN_SMEM_FLOATS * 4>>>();

    // group norm + sigmoid gate -> y (in d_g)
    gate_kernel<<<S_LEN, 256>>>(gnw);

    // out = y @ dense_w^T
    sgemm_tn<false><<<dim3(HDTOT / 128, S_LEN / 128), 256>>>(
        p_g, dens_w, nullptr, out, S_LEN, HDTOT, HID);
}

// round 4
// speedup vs baseline: 2.5885x; 2.5885x over previous
#include <cuda_runtime.h>
#include <cuda_bf16.h>
#include <math.h>
#include <stdint.h>

// ---------------------------------------------------------------------------
// Problem constants
// ---------------------------------------------------------------------------
#define S_LEN   8192
#define HID     2048
#define NH      16
#define HD      128
#define BLK     256
#define NC      32
#define HDTOT   2048
#define QKV_N   6144
#define EPS     1e-5f
#define SCALE_Q 0.08838834764831845f

// split-K GEMM constants
#define GK      6144          // 3 * HID (hi | lo | hi folding)
#define BKG     64
#define NSTEP   96            // GK / BKG
#define GSTG    3
#define STAGE_BYTES (128*BKG*2 + 128*BKG*2)   // 32768
#define GEMM_SMEM   (GSTG * STAGE_BYTES)      // 98304

// ---------------------------------------------------------------------------
// Scratch (static device globals; no allocation allowed)
// ---------------------------------------------------------------------------
__device__ float d_qkv [ (size_t)S_LEN * QKV_N ];
__device__ float d_attn[ (size_t)S_LEN * HDTOT ];
__device__ float d_g   [ (size_t)S_LEN * HDTOT ];
__device__ float d_kvc [ (size_t)NC * NH * HD * HD ];
__device__ float d_kvs [ (size_t)NC * NH * HD * HD ];

// bf16 split operands
__device__ __nv_bfloat16 d_hs_s  [ (size_t)S_LEN * GK ];
__device__ __nv_bfloat16 d_qkvw_s[ (size_t)QKV_N * GK ];
__device__ __nv_bfloat16 d_gw_s  [ (size_t)HDTOT * GK ];
__device__ __nv_bfloat16 d_dw_s  [ (size_t)HDTOT * GK ];
__device__ __nv_bfloat16 d_y_s   [ (size_t)S_LEN * GK ];

__device__ float c_invfreq[64];
__device__ float c_slopes[16];

// ---------------------------------------------------------------------------
// PTX helpers (sm_80+ only; no 'a'-features — toolchain targets plain sm_103)
// ---------------------------------------------------------------------------
__device__ __forceinline__ uint32_t smem_u32(const void* p) {
    uint32_t a;
    asm("{ .reg .u64 t; cvta.to.shared.u64 t, %1; cvt.u32.u64 %0, t; }" : "=r"(a) : "l"(p));
    return a;
}

__device__ __forceinline__ void cp_async16(uint32_t dst, const void* src) {
    asm volatile("cp.async.cg.shared.global [%0], [%1], 16;"
                 :: "r"(dst), "l"(__cvta_generic_to_global(src)) : "memory");
}
#define CP_COMMIT() asm volatile("cp.async.commit_group;" ::: "memory")

__device__ __forceinline__ void ldsm_x4(uint32_t& r0, uint32_t& r1,
                                        uint32_t& r2, uint32_t& r3, uint32_t addr) {
    asm volatile("ldmatrix.sync.aligned.m8n8.x4.shared.b16 {%0,%1,%2,%3}, [%4];"
                 : "=r"(r0), "=r"(r1), "=r"(r2), "=r"(r3) : "r"(addr));
}

__device__ __forceinline__ void mma_bf16(float* d, uint32_t a0, uint32_t a1,
                                         uint32_t a2, uint32_t a3,
                                         uint32_t b0, uint32_t b1) {
    asm volatile("mma.sync.aligned.m16n8k16.row.col.f32.bf16.bf16.f32 "
                 "{%0,%1,%2,%3}, {%4,%5,%6,%7}, {%8,%9}, {%0,%1,%2,%3};"
                 : "+f"(d[0]), "+f"(d[1]), "+f"(d[2]), "+f"(d[3])
                 : "r"(a0), "r"(a1), "r"(a2), "r"(a3), "r"(b0), "r"(b1));
}

#define SW128(o) ((o) ^ (((o) >> 3) & 0x70))

// ---------------------------------------------------------------------------
// Tables
// ---------------------------------------------------------------------------
__global__ void init_tables_kernel() {
    int t = threadIdx.x;
    if (t < 64) {
        double e = ((double)(2 * t) / 128.0) * log(600000.0);
        c_invfreq[t] = (float)exp(-e);
    }
    if (t < 16) {
        double s = exp2(-0.5 * (double)(t + 1));
        c_slopes[t] = (float)(s * (1.0 - 0.0 / 19.0 + 1e-5));
    }
}

// ---------------------------------------------------------------------------
// fp32 -> split-bf16 conversion (K: 2048 -> 6144)
//  A pattern (isA=1): [hi | lo | hi]   B pattern: [hi | hi | lo]
// ---------------------------------------------------------------------------
__global__ __launch_bounds__(256)
void split_kernel(const float* __restrict__ src, __nv_bfloat16* __restrict__ dst, int isA)
{
    size_t idx = ((size_t)blockIdx.x * 256 + threadIdx.x) * 8;
    size_t r = idx >> 11;
    int    k = (int)(idx & 2047);

    float x[8];
    *(float4*)&x[0] = *(const float4*)&src[idx];
    *(float4*)&x[4] = *(const float4*)&src[idx + 4];

    __nv_bfloat16 hi[8], lo[8];
#pragma unroll
    for (int j = 0; j < 8; j++) {
        hi[j] = __float2bfloat16(x[j]);
        lo[j] = __float2bfloat16(x[j] - __bfloat162float(hi[j]));
    }
    __nv_bfloat16* base = dst + r * GK + k;
    *(uint4*)(base)        = *(uint4*)hi;
    *(uint4*)(base + 2048) = isA ? *(uint4*)lo : *(uint4*)hi;
    *(uint4*)(base + 4096) = isA ? *(uint4*)hi : *(uint4*)lo;
}

// ---------------------------------------------------------------------------
// HMMA GEMM: C[M,N] = A'[M,GK] * B'[N,GK]^T (+bias), fp32 out.
// 128x128 tile / CTA, 256 threads (8 warps, 2x4), BK=64, 3-stage cp.async.
// ---------------------------------------------------------------------------
__device__ __forceinline__ void g_load_stage(uint32_t sA,
                                             const __nv_bfloat16* ga,
                                             const __nv_bfloat16* gb, int k0)
{
    const int t = threadIdx.x;
#pragma unroll
    for (int i = 0; i < 4; i++) {
        int c   = t + i * 256;            // 0..1023
        int row = c >> 3;                 // 0..127
        int ch  = c & 7;                  // 16B chunk
        uint32_t off = SW128(row * 128 + ch * 16);
        cp_async16(sA + off,         ga + (size_t)row * GK + k0 + ch * 8);
        cp_async16(sA + 16384 + off, gb + (size_t)row * GK + k0 + ch * 8);
    }
    CP_COMMIT();
}

template <bool HAS_BIAS>
__global__ __launch_bounds__(256, 2)
void hmma_gemm(const __nv_bfloat16* __restrict__ A, const __nv_bfloat16* __restrict__ B,
               const float* __restrict__ bias, float* __restrict__ C, int N)
{
    extern __shared__ char smraw[];
    const uint32_t sbase = smem_u32(smraw);
    const int tid = threadIdx.x;
    const int wid = tid >> 5;
    const int lid = tid & 31;
    const int wm  = wid >> 2;      // 0..1
    const int wn  = wid & 3;       // 0..3

    // supertiled block mapping: groups of 8 M-tiles walk all N-tiles (L2 reuse)
    const int Nt  = N >> 7;
    const int bid = blockIdx.x;
    const int g   = bid / (8 * Nt);
    const int rem = bid % (8 * Nt);
    const int tm  = g * 8 + (rem & 7);
    const int tn  = rem >> 3;

    const __nv_bfloat16* ga = A + (size_t)tm * 128 * GK;
    const __nv_bfloat16* gb = B + (size_t)tn * 128 * GK;

    float acc[4][4][4];
#pragma unroll
    for (int i = 0; i < 4; i++)
#pragma unroll
        for (int j = 0; j < 4; j++)
#pragma unroll
            for (int k = 0; k < 4; k++) acc[i][j][k] = 0.f;

    // prologue: fill all 3 stages
#pragma unroll
    for (int s = 0; s < GSTG; s++)
        g_load_stage(sbase + s * STAGE_BYTES, ga, gb, s * BKG);

    // ldmatrix lane-address components (constant across k-steps)
    const int arow = wm * 64 + (lid & 15);     // + mt*16
    const int akb  = (lid >> 4) * 16;          // byte offset for k half (8 elems)
    const int bg   = lid >> 3;                 // 0..3
    const int brow = wn * 32 + ((bg >> 1) * 8) + (lid & 7);   // + bp*16
    const int bkb  = (bg & 1) * 16;

    for (int it = 0; it < NSTEP; it++) {
        const int remi = NSTEP - 1 - it;
        if      (remi >= 2) asm volatile("cp.async.wait_group 2;" ::: "memory");
        else if (remi == 1) asm volatile("cp.async.wait_group 1;" ::: "memory");
        else                asm volatile("cp.async.wait_group 0;" ::: "memory");
        __syncthreads();

        const uint32_t sA = sbase + (it % GSTG) * STAGE_BYTES;
        const uint32_t sB = sA + 16384;

#pragma unroll
        for (int kk = 0; kk < BKG; kk += 16) {
            uint32_t a[4][4];
#pragma unroll
            for (int mt = 0; mt < 4; mt++) {
                uint32_t off = SW128((uint32_t)(arow + mt * 16) * 128 + kk * 2 + akb);
                ldsm_x4(a[mt][0], a[mt][1], a[mt][2], a[mt][3], sA + off);
            }
            uint32_t b[4][2];
#pragma unroll
            for (int bp = 0; bp < 2; bp++) {
                uint32_t off = SW128((uint32_t)(brow + bp * 16) * 128 + kk * 2 + bkb);
                uint32_t r0, r1, r2, r3;
                ldsm_x4(r0, r1, r2, r3, sB + off);
                b[bp * 2][0] = r0;     b[bp * 2][1] = r1;
                b[bp * 2 + 1][0] = r2; b[bp * 2 + 1][1] = r3;
            }
#pragma unroll
            for (int mt = 0; mt < 4; mt++)
#pragma unroll
                for (int nt = 0; nt < 4; nt++)
                    mma_bf16(acc[mt][nt], a[mt][0], a[mt][1], a[mt][2], a[mt][3],
                             b[nt][0], b[nt][1]);
        }

        __syncthreads();   // all warps done with this stage before reload
        if (it + GSTG < NSTEP)
            g_load_stage(sA, ga, gb, (it + GSTG) * BKG);
    }

    // epilogue: direct fp32 stores (+bias)
    const int r0 = lid >> 2;          // 0..7
    const int c0 = (lid & 3) * 2;
    float2 bb[4];
    if (HAS_BIAS) {
#pragma unroll
        for (int nt = 0; nt < 4; nt++) {
            int cb = tn * 128 + wn * 32 + nt * 8 + c0;
            bb[nt].x = __ldg(&bias[cb]);
            bb[nt].y = __ldg(&bias[cb + 1]);
        }
    }
#pragma unroll
    for (int mt = 0; mt < 4; mt++) {
        int rowa = tm * 128 + wm * 64 + mt * 16 + r0;
#pragma unroll
        for (int nt = 0; nt < 4; nt++) {
            int col = tn * 128 + wn * 32 + nt * 8 + c0;
            float2 v0, v1;
            v0.x = acc[mt][nt][0]; v0.y = acc[mt][nt][1];
            v1.x = acc[mt][nt][2]; v1.y = acc[mt][nt][3];
            if (HAS_BIAS) {
                v0.x += bb[nt].x; v0.y += bb[nt].y;
                v1.x += bb[nt].x; v1.y += bb[nt].y;
            }
            *(float2*)&C[(size_t)rowa * N + col]       = v0;
            *(float2*)&C[(size_t)(rowa + 8) * N + col] = v1;
        }
    }
}

// ---------------------------------------------------------------------------
// Per-head RMSNorm + RoPE + q-scale, in place on d_qkv.
// ---------------------------------------------------------------------------
__global__ __launch_bounds__(128)
void normrope_kernel(const int* __restrict__ positions,
                     const float* __restrict__ qw,
                     const float* __restrict__ kw)
{
    int s = blockIdx.x;
    int h = blockIdx.y;
    int d = threadIdx.x;
    int lane = d & 31;
    int wrp  = d >> 5;

    size_t qoff = (size_t)s * QKV_N + h * HD + d;
    size_t koff = qoff + HDTOT;
    float qv = d_qkv[qoff];
    float kv = d_qkv[koff];

    float sq = qv * qv, sk = kv * kv;
#pragma unroll
    for (int off = 16; off > 0; off >>= 1) {
        sq += __shfl_xor_sync(0xffffffffu, sq, off);
        sk += __shfl_xor_sync(0xffffffffu, sk, off);
    }
    __shared__ float redq[4], redk[4];
    if (lane == 0) { redq[wrp] = sq; redk[wrp] = sk; }
    __syncthreads();
    float msq = (redq[0] + redq[1] + redq[2] + redq[3]) * (1.f / 128.f);
    float msk = (redk[0] + redk[1] + redk[2] + redk[3]) * (1.f / 128.f);

    float qn = qv * rsqrtf(msq + EPS) * qw[d];
    float kn = kv * rsqrtf(msk + EPS) * kw[d];

    __shared__ float qs[128], ks[128];
    qs[d] = qn; ks[d] = kn;
    __syncthreads();

    int i = d & 63;
    float ang = (float)positions[s] * c_invfreq[i];
    float sn, cs;
    sincosf(ang, &sn, &cs);

    float q1 = qs[i], q2 = qs[i + 64];
    float k1 = ks[i], k2 = ks[i + 64];
    float oq = (d < 64) ? (q1 * cs - q2 * sn) : (q2 * cs + q1 * sn);
    float ok = (d < 64) ? (k1 * cs - k2 * sn) : (k2 * cs + k1 * sn);

    d_qkv[qoff] = oq * SCALE_Q;
    d_qkv[koff] = ok;
}

// ---------------------------------------------------------------------------
// Phase 1: per-chunk KV contribution
// ---------------------------------------------------------------------------
__global__ __launch_bounds__(256)
void chunk_kv_kernel()
{
    __shared__ float ks[32][128];
    __shared__ float vs[32][128];

    int c = blockIdx.x, h = blockIdx.y;
    int tid = threadIdx.x;
    int tx = tid & 15, ty = tid >> 4;
    float slope = c_slopes[h];

    float acc[8][8];
#pragma unroll
    for (int i = 0; i < 8; i++)
#pragma unroll
        for (int j = 0; j < 8; j++) acc[i][j] = 0.f;

    for (int jt = 0; jt < BLK; jt += 32) {
#pragma unroll
        for (int l = 0; l < 4; l++) {
            int idx = tid + l * 256;
            int r   = idx >> 5;
            int dq  = (idx & 31) * 4;
            int tok = c * BLK + jt + r;
            float kd = expf(-slope * (float)(BLK - 1 - (jt + r)));
            size_t kb = (size_t)tok * QKV_N + HDTOT + h * HD + dq;
            size_t vb = (size_t)tok * QKV_N + 2 * HDTOT + h * HD + dq;
            float4 kvv = *(const float4*)&d_qkv[kb];
            float4 vvv = *(const float4*)&d_qkv[vb];
            ks[r][dq + 0] = kvv.x * kd; ks[r][dq + 1] = kvv.y * kd;
            ks[r][dq + 2] = kvv.z * kd; ks[r][dq + 3] = kvv.w * kd;
            *(float4*)&vs[r][dq] = vvv;
        }
        __syncthreads();

#pragma unroll 8
        for (int jj = 0; jj < 32; jj++) {
            float a[8], b[8];
            *(float4*)&a[0] = *(const float4*)&ks[jj][ty * 8];
            *(float4*)&a[4] = *(const float4*)&ks[jj][ty * 8 + 4];
            *(float4*)&b[0] = *(const float4*)&vs[jj][tx * 8];
            *(float4*)&b[4] = *(const float4*)&vs[jj][tx * 8 + 4];
#pragma unroll
            for (int i = 0; i < 8; i++)
#pragma unroll
                for (int j = 0; j < 8; j++)
                    acc[i][j] += a[i] * b[j];
        }
        __syncthreads();
    }

    size_t base = ((size_t)(c * NH + h) * HD) * HD;
#pragma unroll
    for (int i = 0; i < 8; i++) {
        size_t o = base + (size_t)(ty * 8 + i) * HD + tx * 8;
        *(float4*)&d_kvc[o]     = *(float4*)&acc[i][0];
        *(float4*)&d_kvc[o + 4] = *(float4*)&acc[i][4];
    }
}

// ---------------------------------------------------------------------------
// Phase 1b: sequential scan over chunks
// ---------------------------------------------------------------------------
__global__ __launch_bounds__(256)
void kv_scan_kernel()
{
    int p  = blockIdx.x * 256 + threadIdx.x;
    int h  = p >> 14;
    int de = p & 16383;
    float bd = expf(-c_slopes[h] * (float)BLK);
    float st = 0.f;
#pragma unroll 1
    for (int c = 0; c < NC; c++) {
        size_t o = (((size_t)(c * NH + h)) << 14) + de;
        d_kvs[o] = st;
        st = bd * st + d_kvc[o];
    }
}

// ---------------------------------------------------------------------------
// Phase 2: intra + inter attention
// ---------------------------------------------------------------------------
#define ATTN_SMEM_FLOATS (128*68 + 128*68 + 64*128 + 64*68 + 256)

__global__ __launch_bounds__(256)
void attn_block_kernel()
{
    extern __shared__ float sm[];
    float* qT  = sm;
    float* kT  = qT + 128 * 68;
    float* vS  = kT + 128 * 68;
    float* sT  = vS + 64 * 128;
    float* tbl = sT + 64 * 68;

    const int rb  = blockIdx.x;
    const int c   = blockIdx.y;
    const int h   = blockIdx.z;
    const int tid = threadIdx.x;
    const float slope = c_slopes[h];

    if (tid < 256) tbl[tid] = expf(-slope * (float)tid);

    const int s0 = c * BLK + rb * 64;

#pragma unroll
    for (int l = 0; l < 8; l++) {
        int idx = tid + l * 256;
        int r   = idx >> 5;
        int dq  = (idx & 31) * 4;
        float4 v = *(const float4*)&d_qkv[(size_t)(s0 + r) * QKV_N + h * HD + dq];
        qT[(dq + 0) * 68 + r] = v.x; qT[(dq + 1) * 68 + r] = v.y;
        qT[(dq + 2) * 68 + r] = v.z; qT[(dq + 3) * 68 + r] = v.w;
    }

    const int txS = tid & 15,  tyS = tid >> 4;
    const int i0  = tyS * 4;
    const int j0  = txS * 4;
    const int e0  = txS * 8;

    float acc[4][8];
#pragma unroll
    for (int i = 0; i < 4; i++)
#pragma unroll
        for (int j = 0; j < 8; j++) acc[i][j] = 0.f;

    for (int jt = 0; jt <= rb; jt++) {
        __syncthreads();
        int t0 = c * BLK + jt * 64;
#pragma unroll
        for (int l = 0; l < 8; l++) {
            int idx = tid + l * 256;
            int r   = idx >> 5;
            int dq  = (idx & 31) * 4;
            float4 kv = *(const float4*)&d_qkv[(size_t)(t0 + r) * QKV_N + HDTOT + h * HD + dq];
            kT[(dq + 0) * 68 + r] = kv.x; kT[(dq + 1) * 68 + r] = kv.y;
            kT[(dq + 2) * 68 + r] = kv.z; kT[(dq + 3) * 68 + r] = kv.w;
            float4 vv = *(const float4*)&d_qkv[(size_t)(t0 + r) * QKV_N + 2 * HDTOT + h * HD + dq];
            *(float4*)&vS[r * 128 + dq] = vv;
        }
        __syncthreads();

        float accS[4][4];
#pragma unroll
        for (int i = 0; i < 4; i++)
#pragma unroll
            for (int j = 0; j < 4; j++) accS[i][j] = 0.f;

#pragma unroll 4
        for (int dd = 0; dd < 128; dd++) {
            float a[4], b[4];
            *(float4*)a = *(const float4*)&qT[dd * 68 + i0];
            *(float4*)b = *(const float4*)&kT[dd * 68 + j0];
#pragma unroll
            for (int i = 0; i < 4; i++)
#pragma unroll
                for (int j = 0; j < 4; j++)
                    accS[i][j] += a[i] * b[j];
        }

#pragma unroll
        for (int i = 0; i < 4; i++) {
#pragma unroll
            for (int j = 0; j < 4; j++) {
                int dif = (rb * 64 + i0 + i) - (jt * 64 + j0 + j);
                float vsc = (dif >= 0) ? accS[i][j] * tbl[dif] : 0.f;
                sT[(j0 + j) * 68 + (i0 + i)] = vsc;
            }
        }
        __syncthreads();

#pragma unroll 4
        for (int jj = 0; jj < 64; jj++) {
            float a[4], b[8];
            *(float4*)a     = *(const float4*)&sT[jj * 68 + i0];
            *(float4*)&b[0] = *(const float4*)&vS[jj * 128 + e0];
            *(float4*)&b[4] = *(const float4*)&vS[jj * 128 + e0 + 4];
#pragma unroll
            for (int i = 0; i < 4; i++)
#pragma unroll
                for (int j = 0; j < 8; j++)
                    acc[i][j] += a[i] * b[j];
        }
    }

    float qd[4];
#pragma unroll
    for (int i = 0; i < 4; i++)
        qd[i] = expf(-slope * (float)(rb * 64 + i0 + i + 1));

    size_t kvbase = (((size_t)(c * NH + h)) << 14);
    for (int dt = 0; dt < 4; dt++) {
        __syncthreads();
#pragma unroll
        for (int l = 0; l < 4; l++) {
            int idx = tid + l * 256;
            int r   = idx >> 5;
            int dq  = (idx & 31) * 4;
            *(float4*)&vS[r * 128 + dq] =
                *(const float4*)&d_kvs[kvbase + (size_t)(dt * 32 + r) * HD + dq];
        }
        __syncthreads();

#pragma unroll 4
        for (int dd = 0; dd < 32; dd++) {
            float a[4], b[8];
            *(float4*)a = *(const float4*)&qT[(dt * 32 + dd) * 68 + i0];
#pragma unroll
            for (int i = 0; i < 4; i++) a[i] *= qd[i];
            *(float4*)&b[0] = *(const float4*)&vS[dd * 128 + e0];
            *(float4*)&b[4] = *(const float4*)&vS[dd * 128 + e0 + 4];
#pragma unroll
            for (int i = 0; i < 4; i++)
#pragma unroll
                for (int j = 0; j < 8; j++)
                    acc[i][j] += a[i] * b[j];
        }
    }

#pragma unroll
    for (int i = 0; i < 4; i++) {
        size_t base = (size_t)(s0 + i0 + i) * HDTOT + h * HD + e0;
        *(float4*)&d_attn[base]     = *(float4*)&acc[i][0];
        *(float4*)&d_attn[base + 4] = *(float4*)&acc[i][4];
    }
}

// ---------------------------------------------------------------------------
// Group-RMSNorm + sigmoid gating -> split-bf16 y (A operand for dense GEMM)
// ---------------------------------------------------------------------------
__global__ __launch_bounds__(256)
void gate_kernel(const float* __restrict__ gnw)
{
    int s = blockIdx.x;
    int t = threadIdx.x;
    size_t base = (size_t)s * HDTOT + t * 8;

    float a[8];
    *(float4*)&a[0] = *(const float4*)&d_attn[base];
    *(float4*)&a[4] = *(const float4*)&d_attn[base + 4];

    float ss = 0.f;
#pragma unroll
    for (int j = 0; j < 8; j++) ss += a[j] * a[j];
#pragma unroll
    for (int off = 16; off > 0; off >>= 1)
        ss += __shfl_xor_sync(0xffffffffu, ss, off);
    float rstd = rsqrtf(ss * (1.f / 256.f) + EPS);

    float gv[8];
    *(float4*)&gv[0] = *(const float4*)&d_g[base];
    *(float4*)&gv[4] = *(const float4*)&d_g[base + 4];

    __nv_bfloat16 hi[8], lo[8];
#pragma unroll
    for (int j = 0; j < 8; j++) {
        float sig = 1.f / (1.f + expf(-gv[j]));
        float y = a[j] * rstd * gnw[t * 8 + j] * sig;
        hi[j] = __float2bfloat16(y);
        lo[j] = __float2bfloat16(y - __bfloat162float(hi[j]));
    }
    __nv_bfloat16* dst = d_y_s + (size_t)s * GK + t * 8;
    *(uint4*)(dst)        = *(uint4*)hi;
    *(uint4*)(dst + 2048) = *(uint4*)lo;
    *(uint4*)(dst + 4096) = *(uint4*)hi;
}

// ---------------------------------------------------------------------------
// Launch
// ---------------------------------------------------------------------------
extern "C" void kernel_launch(void* const* d_in, const int* in_sizes, int n_in,
                              void* d_out, int out_size)
{
    const float* hs     = (const float*)d_in[0];
    const int*   pos    = (const int*)  d_in[1];
    const float* qkv_w  = (const float*)d_in[2];
    const float* qkv_b  = (const float*)d_in[3];
    const float* qnw    = (const float*)d_in[4];
    const float* knw    = (const float*)d_in[5];
    const float* g_w    = (const float*)d_in[6];
    const float* gnw    = (const float*)d_in[7];
    const float* dens_w = (const float*)d_in[8];
    float* out = (float*)d_out;

    float *p_qkv, *p_g;
    __nv_bfloat16 *p_hs_s, *p_qkvw_s, *p_gw_s, *p_dw_s, *p_y_s;
    cudaGetSymbolAddress((void**)&p_qkv,    d_qkv);
    cudaGetSymbolAddress((void**)&p_g,      d_g);
    cudaGetSymbolAddress((void**)&p_hs_s,   d_hs_s);
    cudaGetSymbolAddress((void**)&p_qkvw_s, d_qkvw_s);
    cudaGetSymbolAddress((void**)&p_gw_s,   d_gw_s);
    cudaGetSymbolAddress((void**)&p_dw_s,   d_dw_s);
    cudaGetSymbolAddress((void**)&p_y_s,    d_y_s);

    static_assert(ATTN_SMEM_FLOATS * 4 < 227 * 1024, "smem");
    cudaFuncSetAttribute(attn_block_kernel,
                         cudaFuncAttributeMaxDynamicSharedMemorySize,
                         ATTN_SMEM_FLOATS * 4);
    cudaFuncSetAttribute(hmma_gemm<true>,
                         cudaFuncAttributeMaxDynamicSharedMemorySize, GEMM_SMEM);
    cudaFuncSetAttribute(hmma_gemm<false>,
                         cudaFuncAttributeMaxDynamicSharedMemorySize, GEMM_SMEM);

    init_tables_kernel<<<1, 64>>>();

    // split conversions
    split_kernel<<<(S_LEN * HID) / (256 * 8), 256>>>(hs,     p_hs_s,   1);
    split_kernel<<<(QKV_N * HID) / (256 * 8), 256>>>(qkv_w,  p_qkvw_s, 0);
    split_kernel<<<(HDTOT * HID) / (256 * 8), 256>>>(g_w,    p_gw_s,   0);
    split_kernel<<<(HDTOT * HID) / (256 * 8), 256>>>(dens_w, p_dw_s,   0);

    // qkv = hs @ qkv_w^T + b   (tensor cores, 3xBF16 split)
    hmma_gemm<true><<<(S_LEN / 128) * (QKV_N / 128), 256, GEMM_SMEM>>>(
        p_hs_s, p_qkvw_s, qkv_b, p_qkv, QKV_N);

    // g = hs @ g_w^T
    hmma_gemm<false><<<(S_LEN / 128) * (HDTOT / 128), 256, GEMM_SMEM>>>(
        p_hs_s, p_gw_s, nullptr, p_g, HDTOT);

    normrope_kernel<<<dim3(S_LEN, NH), 128>>>(pos, qnw, knw);

    chunk_kv_kernel<<<dim3(NC, NH), 256>>>();
    kv_scan_kernel<<<(NH * HD * HD) / 256, 256>>>();
    attn_block_kernel<<<dim3(4, NC, NH), 256, ATTN_SMEM_FLOATS * 4>>>();

    gate_kernel<<<S_LEN, 256>>>(gnw);

    // out = y @ dense_w^T
    hmma_gemm<false><<<(S_LEN / 128) * (HDTOT / 128), 256, GEMM_SMEM>>>(
        p_y_s, p_dw_s, nullptr, out, HDTOT);
}

// round 5
// speedup vs baseline: 3.0281x; 1.1698x over previous
#include <cuda_runtime.h>
#include <cuda_bf16.h>
#include <math.h>
#include <stdint.h>

// ---------------------------------------------------------------------------
// Problem constants
// ---------------------------------------------------------------------------
#define S_LEN   8192
#define HID     2048
#define NH      16
#define HD      128
#define BLK     256
#define NC      32
#define HDTOT   2048
#define QKV_N   6144
#define EPS     1e-5f
#define SCALE_Q 0.08838834764831845f

// split-K GEMM constants
#define GK      6144
#define BKG     64
#define NSTEP   96
#define GSTG    3
#define STAGE_BYTES (128*BKG*2 + 128*BKG*2)
#define GEMM_SMEM   (GSTG * STAGE_BYTES)

// attention HMMA smem layout (bytes)
#define AQ_ROW 784                     // 384 bf16 + 8B pad
#define AV_ROW 272                     // 128 bf16 + 8B pad
#define AP_ROW 400                     // 192 bf16 + 8B pad
#define A_SQ   0
#define A_SK   50176                   // 64*784
#define A_SV   (A_SK + 50176)          // v' 192*272 ; kvT occupies [A_SK, A_SK+128*784)
#define A_SP   152576
#define A_STBL (A_SP + 64*400)         // 178176
#define ATTN_SMEM (A_STBL + 1056)      // 179232

// chunk_kv smem
#define C_SK 0
#define C_SV 52224                     // 192*272
#define CHUNK_SMEM 104448

// ---------------------------------------------------------------------------
// Scratch (static device globals; no allocation allowed)
// ---------------------------------------------------------------------------
__device__ float d_qkv [ (size_t)S_LEN * QKV_N ];
__device__ float d_attn[ (size_t)S_LEN * HDTOT ];
__device__ float d_g   [ (size_t)S_LEN * HDTOT ];
__device__ float d_kvc [ (size_t)NC * NH * HD * HD ];   // per-chunk KV^T [c][h][e][d] fp32

// bf16 split operands (big GEMMs)
__device__ __nv_bfloat16 d_hs_s  [ (size_t)S_LEN * GK ];
__device__ __nv_bfloat16 d_qkvw_s[ (size_t)QKV_N * GK ];
__device__ __nv_bfloat16 d_gw_s  [ (size_t)HDTOT * GK ];
__device__ __nv_bfloat16 d_dw_s  [ (size_t)HDTOT * GK ];
__device__ __nv_bfloat16 d_y_s   [ (size_t)S_LEN * GK ];

// bf16 attention operands
__device__ __nv_bfloat16 d_qf   [ (size_t)S_LEN * NH * 384 ];  // [hi|lo|hi]
__device__ __nv_bfloat16 d_kf   [ (size_t)S_LEN * NH * 384 ];  // [hi|hi|lo]
__device__ __nv_bfloat16 d_v2   [ (size_t)S_LEN * NH * 256 ];  // [hi|lo]
__device__ __nv_bfloat16 d_kvs_f[ (size_t)NC * NH * 128 * 384 ]; // KV^T prefix, [e][hi|hi|lo over d]

__device__ float c_invfreq[64];
__device__ float c_slopes[16];

// ---------------------------------------------------------------------------
// PTX helpers (sm_80+ only)
// ---------------------------------------------------------------------------
__device__ __forceinline__ uint32_t smem_u32(const void* p) {
    uint32_t a;
    asm("{ .reg .u64 t; cvta.to.shared.u64 t, %1; cvt.u32.u64 %0, t; }" : "=r"(a) : "l"(p));
    return a;
}
__device__ __forceinline__ void cp_async16(uint32_t dst, const void* src) {
    asm volatile("cp.async.cg.shared.global [%0], [%1], 16;"
                 :: "r"(dst), "l"(__cvta_generic_to_global(src)) : "memory");
}
#define CP_COMMIT() asm volatile("cp.async.commit_group;" ::: "memory")
#define CP_WAIT0()  asm volatile("cp.async.wait_group 0;" ::: "memory")

__device__ __forceinline__ void ldsm_x4(uint32_t& r0, uint32_t& r1,
                                        uint32_t& r2, uint32_t& r3, uint32_t addr) {
    asm volatile("ldmatrix.sync.aligned.m8n8.x4.shared.b16 {%0,%1,%2,%3}, [%4];"
                 : "=r"(r0), "=r"(r1), "=r"(r2), "=r"(r3) : "r"(addr));
}
__device__ __forceinline__ void ldsm_x4_t(uint32_t& r0, uint32_t& r1,
                                          uint32_t& r2, uint32_t& r3, uint32_t addr) {
    asm volatile("ldmatrix.sync.aligned.m8n8.x4.trans.shared.b16 {%0,%1,%2,%3}, [%4];"
                 : "=r"(r0), "=r"(r1), "=r"(r2), "=r"(r3) : "r"(addr));
}
__device__ __forceinline__ void mma_bf16(float* d, uint32_t a0, uint32_t a1,
                                         uint32_t a2, uint32_t a3,
                                         uint32_t b0, uint32_t b1) {
    asm volatile("mma.sync.aligned.m16n8k16.row.col.f32.bf16.bf16.f32 "
                 "{%0,%1,%2,%3}, {%4,%5,%6,%7}, {%8,%9}, {%0,%1,%2,%3};"
                 : "+f"(d[0]), "+f"(d[1]), "+f"(d[2]), "+f"(d[3])
                 : "r"(a0), "r"(a1), "r"(a2), "r"(a3), "r"(b0), "r"(b1));
}

__device__ __forceinline__ void split_bf(float v, __nv_bfloat16& hi, __nv_bfloat16& lo) {
    hi = __float2bfloat16(v);
    lo = __float2bfloat16(v - __bfloat162float(hi));
}
__device__ __forceinline__ uint32_t pack_bf2(__nv_bfloat16 a, __nv_bfloat16 b) {
    __nv_bfloat162 t; t.x = a; t.y = b;
    return *(uint32_t*)&t;
}

#define SW128(o) ((o) ^ (((o) >> 3) & 0x70))

// ---------------------------------------------------------------------------
// Tables
// ---------------------------------------------------------------------------
__global__ void init_tables_kernel() {
    int t = threadIdx.x;
    if (t < 64) {
        double e = ((double)(2 * t) / 128.0) * log(600000.0);
        c_invfreq[t] = (float)exp(-e);
    }
    if (t < 16) {
        double s = exp2(-0.5 * (double)(t + 1));
        c_slopes[t] = (float)(s * (1.0 - 0.0 / 19.0 + 1e-5));
    }
}

// ---------------------------------------------------------------------------
// fp32 -> split-bf16 conversion for the big GEMMs
// ---------------------------------------------------------------------------
__global__ __launch_bounds__(256)
void split_kernel(const float* __restrict__ src, __nv_bfloat16* __restrict__ dst, int isA)
{
    size_t idx = ((size_t)blockIdx.x * 256 + threadIdx.x) * 8;
    size_t r = idx >> 11;
    int    k = (int)(idx & 2047);

    float x[8];
    *(float4*)&x[0] = *(const float4*)&src[idx];
    *(float4*)&x[4] = *(const float4*)&src[idx + 4];

    __nv_bfloat16 hi[8], lo[8];
#pragma unroll
    for (int j = 0; j < 8; j++) split_bf(x[j], hi[j], lo[j]);
    __nv_bfloat16* base = dst + r * GK + k;
    *(uint4*)(base)        = *(uint4*)hi;
    *(uint4*)(base + 2048) = isA ? *(uint4*)lo : *(uint4*)hi;
    *(uint4*)(base + 4096) = isA ? *(uint4*)hi : *(uint4*)lo;
}

// ---------------------------------------------------------------------------
// HMMA GEMM (unchanged from round 4)
// ---------------------------------------------------------------------------
__device__ __forceinline__ void g_load_stage(uint32_t sA,
                                             const __nv_bfloat16* ga,
                                             const __nv_bfloat16* gb, int k0)
{
    const int t = threadIdx.x;
#pragma unroll
    for (int i = 0; i < 4; i++) {
        int c   = t + i * 256;
        int row = c >> 3;
        int ch  = c & 7;
        uint32_t off = SW128(row * 128 + ch * 16);
        cp_async16(sA + off,         ga + (size_t)row * GK + k0 + ch * 8);
        cp_async16(sA + 16384 + off, gb + (size_t)row * GK + k0 + ch * 8);
    }
    CP_COMMIT();
}

template <bool HAS_BIAS>
__global__ __launch_bounds__(256, 2)
void hmma_gemm(const __nv_bfloat16* __restrict__ A, const __nv_bfloat16* __restrict__ B,
               const float* __restrict__ bias, float* __restrict__ C, int N)
{
    extern __shared__ char smraw[];
    const uint32_t sbase = smem_u32(smraw);
    const int tid = threadIdx.x;
    const int wid = tid >> 5;
    const int lid = tid & 31;
    const int wm  = wid >> 2;
    const int wn  = wid & 3;

    const int Nt  = N >> 7;
    const int bid = blockIdx.x;
    const int g   = bid / (8 * Nt);
    const int rem = bid % (8 * Nt);
    const int tm  = g * 8 + (rem & 7);
    const int tn  = rem >> 3;

    const __nv_bfloat16* ga = A + (size_t)tm * 128 * GK;
    const __nv_bfloat16* gb = B + (size_t)tn * 128 * GK;

    float acc[4][4][4];
#pragma unroll
    for (int i = 0; i < 4; i++)
#pragma unroll
        for (int j = 0; j < 4; j++)
#pragma unroll
            for (int k = 0; k < 4; k++) acc[i][j][k] = 0.f;

#pragma unroll
    for (int s = 0; s < GSTG; s++)
        g_load_stage(sbase + s * STAGE_BYTES, ga, gb, s * BKG);

    const int arow = wm * 64 + (lid & 15);
    const int akb  = (lid >> 4) * 16;
    const int bg   = lid >> 3;
    const int brow = wn * 32 + ((bg >> 1) * 8) + (lid & 7);
    const int bkb  = (bg & 1) * 16;

    for (int it = 0; it < NSTEP; it++) {
        const int remi = NSTEP - 1 - it;
        if      (remi >= 2) asm volatile("cp.async.wait_group 2;" ::: "memory");
        else if (remi == 1) asm volatile("cp.async.wait_group 1;" ::: "memory");
        else                asm volatile("cp.async.wait_group 0;" ::: "memory");
        __syncthreads();

        const uint32_t sA = sbase + (it % GSTG) * STAGE_BYTES;
        const uint32_t sB = sA + 16384;

#pragma unroll
        for (int kk = 0; kk < BKG; kk += 16) {
            uint32_t a[4][4];
#pragma unroll
            for (int mt = 0; mt < 4; mt++) {
                uint32_t off = SW128((uint32_t)(arow + mt * 16) * 128 + kk * 2 + akb);
                ldsm_x4(a[mt][0], a[mt][1], a[mt][2], a[mt][3], sA + off);
            }
            uint32_t b[4][2];
#pragma unroll
            for (int bp = 0; bp < 2; bp++) {
                uint32_t off = SW128((uint32_t)(brow + bp * 16) * 128 + kk * 2 + bkb);
                uint32_t r0, r1, r2, r3;
                ldsm_x4(r0, r1, r2, r3, sB + off);
                b[bp * 2][0] = r0;     b[bp * 2][1] = r1;
                b[bp * 2 + 1][0] = r2; b[bp * 2 + 1][1] = r3;
            }
#pragma unroll
            for (int mt = 0; mt < 4; mt++)
#pragma unroll
                for (int nt = 0; nt < 4; nt++)
                    mma_bf16(acc[mt][nt], a[mt][0], a[mt][1], a[mt][2], a[mt][3],
                             b[nt][0], b[nt][1]);
        }

        __syncthreads();
        if (it + GSTG < NSTEP)
            g_load_stage(sA, ga, gb, (it + GSTG) * BKG);
    }

    const int r0 = lid >> 2;
    const int c0 = (lid & 3) * 2;
    float2 bb[4];
    if (HAS_BIAS) {
#pragma unroll
        for (int nt = 0; nt < 4; nt++) {
            int cb = tn * 128 + wn * 32 + nt * 8 + c0;
            bb[nt].x = __ldg(&bias[cb]);
            bb[nt].y = __ldg(&bias[cb + 1]);
        }
    }
#pragma unroll
    for (int mt = 0; mt < 4; mt++) {
        int rowa = tm * 128 + wm * 64 + mt * 16 + r0;
#pragma unroll
        for (int nt = 0; nt < 4; nt++) {
            int col = tn * 128 + wn * 32 + nt * 8 + c0;
            float2 v0, v1;
            v0.x = acc[mt][nt][0]; v0.y = acc[mt][nt][1];
            v1.x = acc[mt][nt][2]; v1.y = acc[mt][nt][3];
            if (HAS_BIAS) {
                v0.x += bb[nt].x; v0.y += bb[nt].y;
                v1.x += bb[nt].x; v1.y += bb[nt].y;
            }
            *(float2*)&C[(size_t)rowa * N + col]       = v0;
            *(float2*)&C[(size_t)(rowa + 8) * N + col] = v1;
        }
    }
}

// ---------------------------------------------------------------------------
// Per-head RMSNorm + RoPE + q-scale; emits folded bf16 q/k and split v.
// grid (S, NH), 128 threads.
// ---------------------------------------------------------------------------
__global__ __launch_bounds__(128)
void normrope_kernel(const int* __restrict__ positions,
                     const float* __restrict__ qw,
                     const float* __restrict__ kw)
{
    int s = blockIdx.x;
    int h = blockIdx.y;
    int d = threadIdx.x;
    int lane = d & 31;
    int wrp  = d >> 5;

    size_t qoff = (size_t)s * QKV_N + h * HD + d;
    size_t koff = qoff + HDTOT;
    size_t voff = koff + HDTOT;
    float qv = d_qkv[qoff];
    float kv = d_qkv[koff];
    float vv = d_qkv[voff];

    float sq = qv * qv, sk = kv * kv;
#pragma unroll
    for (int off = 16; off > 0; off >>= 1) {
        sq += __shfl_xor_sync(0xffffffffu, sq, off);
        sk += __shfl_xor_sync(0xffffffffu, sk, off);
    }
    __shared__ float redq[4], redk[4];
    if (lane == 0) { redq[wrp] = sq; redk[wrp] = sk; }
    __syncthreads();
    float msq = (redq[0] + redq[1] + redq[2] + redq[3]) * (1.f / 128.f);
    float msk = (redk[0] + redk[1] + redk[2] + redk[3]) * (1.f / 128.f);

    float qn = qv * rsqrtf(msq + EPS) * qw[d];
    float kn = kv * rsqrtf(msk + EPS) * kw[d];

    __shared__ float qs[128], ks[128];
    qs[d] = qn; ks[d] = kn;
    __syncthreads();

    int i = d & 63;
    float ang = (float)positions[s] * c_invfreq[i];
    float sn, cs;
    sincosf(ang, &sn, &cs);

    float q1 = qs[i], q2 = qs[i + 64];
    float k1 = ks[i], k2 = ks[i + 64];
    float oq = ((d < 64) ? (q1 * cs - q2 * sn) : (q2 * cs + q1 * sn)) * SCALE_Q;
    float ok = (d < 64) ? (k1 * cs - k2 * sn) : (k2 * cs + k1 * sn);

    __nv_bfloat16 qh, ql, kh, kl, vh, vl;
    split_bf(oq, qh, ql);
    split_bf(ok, kh, kl);
    split_bf(vv, vh, vl);

    __nv_bfloat16* qrow = d_qf + ((size_t)s * NH + h) * 384;
    qrow[d] = qh; qrow[128 + d] = ql; qrow[256 + d] = qh;      // A pattern
    __nv_bfloat16* krow = d_kf + ((size_t)s * NH + h) * 384;
    krow[d] = kh; krow[128 + d] = kh; krow[256 + d] = kl;      // B pattern
    __nv_bfloat16* vrow = d_v2 + ((size_t)s * NH + h) * 256;
    vrow[d] = vh; vrow[128 + d] = vl;
}

// ---------------------------------------------------------------------------
// Phase 1 (HMMA): per-chunk KV^T[e][d] = sum_j v[j,e] * (kd[j]*k[j,d])
// grid (NC, NH), 256 threads (8 warps 2x4), warp tile 64x32.
// A = v^T (trans ldmatrix, fold [hi|lo|hi] over j), B = k~^T (trans, [hi|hi|lo]).
// ---------------------------------------------------------------------------
__global__ __launch_bounds__(256, 2)
void chunk_kv_hmma()
{
    extern __shared__ char sm[];
    const uint32_t sb = smem_u32(sm);
    const int tid = threadIdx.x;
    const int wid = tid >> 5, lid = tid & 31;
    const int wm = wid >> 2, wn = wid & 3;
    const int c = blockIdx.x, h = blockIdx.y;
    const float slope = c_slopes[h];

    float acc[4][4][4];
#pragma unroll
    for (int i = 0; i < 4; i++)
#pragma unroll
        for (int j = 0; j < 4; j++)
#pragma unroll
            for (int k = 0; k < 4; k++) acc[i][j][k] = 0.f;

    for (int sub = 0; sub < 4; sub++) {
        __syncthreads();
        const int t0 = c * BLK + sub * 64;
        // loaders: 64 rows x 16 chunks of 16B = 1024 chunks
#pragma unroll
        for (int l = 0; l < 4; l++) {
            int ci = tid + l * 256;
            int j  = ci >> 4;
            int c8 = ci & 15;
            // k: re-split AFTER decay multiply
            const __nv_bfloat16* kfrow = d_kf + ((size_t)(t0 + j) * NH + h) * 384;
            uint4 uh = *(const uint4*)(kfrow + c8 * 8);
            uint4 ul = *(const uint4*)(kfrow + 256 + c8 * 8);
            const __nv_bfloat16* ah = (const __nv_bfloat16*)&uh;
            const __nv_bfloat16* al = (const __nv_bfloat16*)&ul;
            float kd = expf(-slope * (float)(BLK - 1 - (sub * 64 + j)));
            __nv_bfloat16 oh[8], ol[8];
#pragma unroll
            for (int q = 0; q < 8; q++) {
                float t = (__bfloat162float(ah[q]) + __bfloat162float(al[q])) * kd;
                split_bf(t, oh[q], ol[q]);
            }
            char* kb = sm + C_SK + c8 * 16;
            *(uint4*)(kb + (size_t)j * 272)         = *(uint4*)oh;   // hi
            *(uint4*)(kb + (size_t)(j + 64) * 272)  = *(uint4*)oh;   // hi
            *(uint4*)(kb + (size_t)(j + 128) * 272) = *(uint4*)ol;   // lo
            // v: straight copy of hi/lo planes, A pattern [hi|lo|hi]
            const __nv_bfloat16* vrow = d_v2 + ((size_t)(t0 + j) * NH + h) * 256;
            uint4 vh = *(const uint4*)(vrow + c8 * 8);
            uint4 vl = *(const uint4*)(vrow + 128 + c8 * 8);
            char* vb = sm + C_SV + c8 * 16;
            *(uint4*)(vb + (size_t)j * 272)         = vh;
            *(uint4*)(vb + (size_t)(j + 64) * 272)  = vl;
            *(uint4*)(vb + (size_t)(j + 128) * 272) = vh;
        }
        __syncthreads();

#pragma unroll
        for (int ks = 0; ks < 192; ks += 16) {
            uint32_t a[4][4];
#pragma unroll
            for (int mt = 0; mt < 4; mt++) {
                int e0 = wm * 64 + mt * 16;
                uint32_t addr = sb + C_SV +
                    (uint32_t)(ks + (lid >> 4) * 8 + (lid & 7)) * 272 +
                    e0 * 2 + ((lid >> 3) & 1) * 16;
                ldsm_x4_t(a[mt][0], a[mt][1], a[mt][2], a[mt][3], addr);
            }
            uint32_t b[4][2];
#pragma unroll
            for (int nb = 0; nb < 2; nb++) {
                int d0 = wn * 32 + nb * 16;
                uint32_t addr = sb + C_SK +
                    (uint32_t)(ks + ((lid >> 3) & 1) * 8 + (lid & 7)) * 272 +
                    d0 * 2 + (lid >> 4) * 16;
                uint32_t r0, r1, r2, r3;
                ldsm_x4_t(r0, r1, r2, r3, addr);
                b[nb * 2][0] = r0;     b[nb * 2][1] = r1;
                b[nb * 2 + 1][0] = r2; b[nb * 2 + 1][1] = r3;
            }
#pragma unroll
            for (int mt = 0; mt < 4; mt++)
#pragma unroll
                for (int nt = 0; nt < 4; nt++)
                    mma_bf16(acc[mt][nt], a[mt][0], a[mt][1], a[mt][2], a[mt][3],
                             b[nt][0], b[nt][1]);
        }
    }

    // store KV^T fp32 [e][d]
    size_t base = ((size_t)(c * NH + h)) * HD * HD;
#pragma unroll
    for (int mt = 0; mt < 4; mt++) {
        int e = wm * 64 + mt * 16 + (lid >> 2);
#pragma unroll
        for (int nt = 0; nt < 4; nt++) {
            int dd = wn * 32 + nt * 8 + (lid & 3) * 2;
            float2 v0, v1;
            v0.x = acc[mt][nt][0]; v0.y = acc[mt][nt][1];
            v1.x = acc[mt][nt][2]; v1.y = acc[mt][nt][3];
            *(float2*)&d_kvc[base + (size_t)e * HD + dd]       = v0;
            *(float2*)&d_kvc[base + (size_t)(e + 8) * HD + dd] = v1;
        }
    }
}

// ---------------------------------------------------------------------------
// Phase 1b: scan over chunks, emit folded bf16 KV^T prefix states.
// 256 blocks x 256 threads; thread owns (h, e, d4).
// ---------------------------------------------------------------------------
__global__ __launch_bounds__(256)
void kv_scan_kernel()
{
    int p  = blockIdx.x * 256 + threadIdx.x;
    int h  = p >> 12;
    int e  = (p >> 5) & 127;
    int d4 = (p & 31) * 4;
    float bd = expf(-c_slopes[h] * (float)BLK);
    float4 st = make_float4(0.f, 0.f, 0.f, 0.f);
#pragma unroll 1
    for (int c = 0; c < NC; c++) {
        size_t ro = ((size_t)(c * NH + h) * 128 + e);
        __nv_bfloat16 h0, l0, h1, l1, h2, l2, h3, l3;
        split_bf(st.x, h0, l0); split_bf(st.y, h1, l1);
        split_bf(st.z, h2, l2); split_bf(st.w, h3, l3);
        uint2 hp, lp;
        hp.x = pack_bf2(h0, h1); hp.y = pack_bf2(h2, h3);
        lp.x = pack_bf2(l0, l1); lp.y = pack_bf2(l2, l3);
        __nv_bfloat16* orow = d_kvs_f + ro * 384;
        *(uint2*)(orow + d4)       = hp;
        *(uint2*)(orow + 128 + d4) = hp;
        *(uint2*)(orow + 256 + d4) = lp;
        float4 v = *(const float4*)(d_kvc + ro * 128 + d4);
        st.x = bd * st.x + v.x; st.y = bd * st.y + v.y;
        st.z = bd * st.z + v.z; st.w = bd * st.w + v.w;
    }
}

// ---------------------------------------------------------------------------
// Phase 2 (HMMA): inter + intra attention for 64 q rows of one (chunk, head).
// grid (4, NC, NH), 256 threads (8 warps 2x4).
// ---------------------------------------------------------------------------
__global__ __launch_bounds__(256, 1)
void attn_hmma_kernel()
{
    extern __shared__ char sm[];
    const uint32_t sb = smem_u32(sm);
    const int tid = threadIdx.x;
    const int wid = tid >> 5, lid = tid & 31;
    const int wm = wid >> 2, wn = wid & 3;
    const int rb = blockIdx.x, c = blockIdx.y, h = blockIdx.z;
    const float slope = c_slopes[h];
    const int s0 = c * BLK + rb * 64;

    float* tbl = (float*)(sm + A_STBL);
    for (int t = tid; t < 257; t += 256) tbl[t] = expf(-slope * (float)t);

    // load q' (64 x 48 chunks) and kvT (128 x 48 chunks)
#pragma unroll
    for (int l = 0; l < 12; l++) {
        int ci = tid + l * 256;
        int r = ci / 48, c16 = ci % 48;
        cp_async16(sb + A_SQ + r * AQ_ROW + c16 * 16,
                   d_qf + ((size_t)(s0 + r) * NH + h) * 384 + c16 * 8);
    }
    {
        const __nv_bfloat16* kvb = d_kvs_f + ((size_t)(c * NH + h)) * 128 * 384;
#pragma unroll
        for (int l = 0; l < 24; l++) {
            int ci = tid + l * 256;
            int r = ci / 48, c16 = ci % 48;
            cp_async16(sb + A_SK + r * AQ_ROW + c16 * 16,
                       kvb + (size_t)r * 384 + c16 * 8);
        }
    }
    CP_COMMIT();
    CP_WAIT0();
    __syncthreads();

    // ---- INTER: O = qdecay ⊙ (q' @ kvT') ----
    float acc[2][4][4];
#pragma unroll
    for (int i = 0; i < 2; i++)
#pragma unroll
        for (int j = 0; j < 4; j++)
#pragma unroll
            for (int k = 0; k < 4; k++) acc[i][j][k] = 0.f;

    const int bg = lid >> 3;
#pragma unroll
    for (int ks = 0; ks < 384; ks += 16) {
        uint32_t a[2][4];
#pragma unroll
        for (int mt = 0; mt < 2; mt++) {
            uint32_t addr = sb + A_SQ +
                (uint32_t)(wm * 32 + mt * 16 + (lid & 15)) * AQ_ROW +
                ks * 2 + (lid >> 4) * 16;
            ldsm_x4(a[mt][0], a[mt][1], a[mt][2], a[mt][3], addr);
        }
        uint32_t b[4][2];
#pragma unroll
        for (int nb = 0; nb < 2; nb++) {
            int n0 = wn * 32 + nb * 16;
            uint32_t addr = sb + A_SK +
                (uint32_t)(n0 + (bg >> 1) * 8 + (lid & 7)) * AQ_ROW +
                ks * 2 + (bg & 1) * 16;
            uint32_t r0, r1, r2, r3;
            ldsm_x4(r0, r1, r2, r3, addr);
            b[nb * 2][0] = r0;     b[nb * 2][1] = r1;
            b[nb * 2 + 1][0] = r2; b[nb * 2 + 1][1] = r3;
        }
#pragma unroll
        for (int mt = 0; mt < 2; mt++)
#pragma unroll
            for (int nt = 0; nt < 4; nt++)
                mma_bf16(acc[mt][nt], a[mt][0], a[mt][1], a[mt][2], a[mt][3],
                         b[nt][0], b[nt][1]);
    }
    // qdecay row scaling
#pragma unroll
    for (int mt = 0; mt < 2; mt++) {
        int r = wm * 32 + mt * 16 + (lid >> 2);
        float q0 = tbl[rb * 64 + r + 1];
        float q1 = tbl[rb * 64 + r + 9];
#pragma unroll
        for (int nt = 0; nt < 4; nt++) {
            acc[mt][nt][0] *= q0; acc[mt][nt][1] *= q0;
            acc[mt][nt][2] *= q1; acc[mt][nt][3] *= q1;
        }
    }

    // ---- INTRA loop over k/v subtiles ----
    for (int jt = 0; jt <= rb; jt++) {
        __syncthreads();   // everyone done with previous P'/v'/kvT reads
        const int t0 = c * BLK + jt * 64;
#pragma unroll
        for (int l = 0; l < 12; l++) {
            int ci = tid + l * 256;
            int r = ci / 48, c16 = ci % 48;
            cp_async16(sb + A_SK + r * AQ_ROW + c16 * 16,
                       d_kf + ((size_t)(t0 + r) * NH + h) * 384 + c16 * 8);
        }
#pragma unroll
        for (int l = 0; l < 12; l++) {
            int ci = tid + l * 256;
            int r  = ci >> 4;            // 0..191
            int c8 = ci & 15;
            int jj = r & 63;
            int half = r >> 6;           // 0,1 -> hi ; 2 -> lo
            int coloff = (half == 2) ? 128 : 0;
            cp_async16(sb + A_SV + r * AV_ROW + c8 * 16,
                       d_v2 + ((size_t)(t0 + jj) * NH + h) * 256 + coloff + c8 * 8);
        }
        CP_COMMIT();
        CP_WAIT0();
        __syncthreads();

        // scores: 64x64, K=384
        float accS[2][2][4];
#pragma unroll
        for (int i = 0; i < 2; i++)
#pragma unroll
            for (int j = 0; j < 2; j++)
#pragma unroll
                for (int k = 0; k < 4; k++) accS[i][j][k] = 0.f;

#pragma unroll
        for (int ks = 0; ks < 384; ks += 16) {
            uint32_t a[2][4];
#pragma unroll
            for (int mt = 0; mt < 2; mt++) {
                uint32_t addr = sb + A_SQ +
                    (uint32_t)(wm * 32 + mt * 16 + (lid & 15)) * AQ_ROW +
                    ks * 2 + (lid >> 4) * 16;
                ldsm_x4(a[mt][0], a[mt][1], a[mt][2], a[mt][3], addr);
            }
            int n0 = wn * 16;
            uint32_t addr = sb + A_SK +
                (uint32_t)(n0 + (bg >> 1) * 8 + (lid & 7)) * AQ_ROW +
                ks * 2 + (bg & 1) * 16;
            uint32_t b0, b1, b2, b3;
            ldsm_x4(b0, b1, b2, b3, addr);
#pragma unroll
            for (int mt = 0; mt < 2; mt++) {
                mma_bf16(accS[mt][0], a[mt][0], a[mt][1], a[mt][2], a[mt][3], b0, b1);
                mma_bf16(accS[mt][1], a[mt][0], a[mt][1], a[mt][2], a[mt][3], b2, b3);
            }
        }

        // mask + decay + fold P' = [hi | lo | hi]
#pragma unroll
        for (int mt = 0; mt < 2; mt++) {
            int r = wm * 32 + mt * 16 + (lid >> 2);
            int gi0 = rb * 64 + r;
#pragma unroll
            for (int nt = 0; nt < 2; nt++) {
                int cc = wn * 16 + nt * 8 + (lid & 3) * 2;
                int d00 = gi0 - (jt * 64 + cc);
                float v00 = (d00 >= 0) ? accS[mt][nt][0] * tbl[d00]     : 0.f;
                float v01 = (d00 >= 1) ? accS[mt][nt][1] * tbl[d00 - 1] : 0.f;
                int d10 = d00 + 8;
                float v10 = (d10 >= 0) ? accS[mt][nt][2] * tbl[d10]     : 0.f;
                float v11 = (d10 >= 1) ? accS[mt][nt][3] * tbl[d10 - 1] : 0.f;
                __nv_bfloat16 h00, l00, h01, l01, h10, l10, h11, l11;
                split_bf(v00, h00, l00); split_bf(v01, h01, l01);
                split_bf(v10, h10, l10); split_bf(v11, h11, l11);
                uint32_t hp0 = pack_bf2(h00, h01), lp0 = pack_bf2(l00, l01);
                uint32_t hp1 = pack_bf2(h10, h11), lp1 = pack_bf2(l10, l11);
                char* b0p = sm + A_SP + r * AP_ROW + cc * 2;
                *(uint32_t*)(b0p)       = hp0;
                *(uint32_t*)(b0p + 128) = lp0;
                *(uint32_t*)(b0p + 256) = hp0;
                char* b1p = b0p + 8 * AP_ROW;
                *(uint32_t*)(b1p)       = hp1;
                *(uint32_t*)(b1p + 128) = lp1;
                *(uint32_t*)(b1p + 256) = hp1;
            }
        }
        __syncthreads();   // P' complete

        // PV: O += P'(64x192) @ v'(trans)
#pragma unroll
        for (int ks = 0; ks < 192; ks += 16) {
            uint32_t a[2][4];
#pragma unroll
            for (int mt = 0; mt < 2; mt++) {
                uint32_t addr = sb + A_SP +
                    (uint32_t)(wm * 32 + mt * 16 + (lid & 15)) * AP_ROW +
                    ks * 2 + (lid >> 4) * 16;
                ldsm_x4(a[mt][0], a[mt][1], a[mt][2], a[mt][3], addr);
            }
            uint32_t b[4][2];
#pragma unroll
            for (int nb = 0; nb < 2; nb++) {
                int e0 = wn * 32 + nb * 16;
                uint32_t addr = sb + A_SV +
                    (uint32_t)(ks + ((lid >> 3) & 1) * 8 + (lid & 7)) * AV_ROW +
                    e0 * 2 + (lid >> 4) * 16;
                uint32_t r0, r1, r2, r3;
                ldsm_x4_t(r0, r1, r2, r3, addr);
                b[nb * 2][0] = r0;     b[nb * 2][1] = r1;
                b[nb * 2 + 1][0] = r2; b[nb * 2 + 1][1] = r3;
            }
#pragma unroll
            for (int mt = 0; mt < 2; mt++)
#pragma unroll
                for (int nt = 0; nt < 4; nt++)
                    mma_bf16(acc[mt][nt], a[mt][0], a[mt][1], a[mt][2], a[mt][3],
                             b[nt][0], b[nt][1]);
        }
    }

    // store O
#pragma unroll
    for (int mt = 0; mt < 2; mt++) {
        int r = wm * 32 + mt * 16 + (lid >> 2);
#pragma unroll
        for (int nt = 0; nt < 4; nt++) {
            int col = wn * 32 + nt * 8 + (lid & 3) * 2;
            float2 v0, v1;
            v0.x = acc[mt][nt][0]; v0.y = acc[mt][nt][1];
            v1.x = acc[mt][nt][2]; v1.y = acc[mt][nt][3];
            *(float2*)&d_attn[(size_t)(s0 + r) * HDTOT + h * HD + col]     = v0;
            *(float2*)&d_attn[(size_t)(s0 + r + 8) * HDTOT + h * HD + col] = v1;
        }
    }
}

// ---------------------------------------------------------------------------
// Group-RMSNorm + sigmoid gating -> split-bf16 y
// ---------------------------------------------------------------------------
__global__ __launch_bounds__(256)
void gate_kernel(const float* __restrict__ gnw)
{
    int s = blockIdx.x;
    int t = threadIdx.x;
    size_t base = (size_t)s * HDTOT + t * 8;

    float a[8];
    *(float4*)&a[0] = *(const float4*)&d_attn[base];
    *(float4*)&a[4] = *(const float4*)&d_attn[base + 4];

    float ss = 0.f;
#pragma unroll
    for (int j = 0; j < 8; j++) ss += a[j] * a[j];
#pragma unroll
    for (int off = 16; off > 0; off >>= 1)
        ss += __shfl_xor_sync(0xffffffffu, ss, off);
    float rstd = rsqrtf(ss * (1.f / 256.f) + EPS);

    float gv[8];
    *(float4*)&gv[0] = *(const float4*)&d_g[base];
    *(float4*)&gv[4] = *(const float4*)&d_g[base + 4];

    __nv_bfloat16 hi[8], lo[8];
#pragma unroll
    for (int j = 0; j < 8; j++) {
        float sig = 1.f / (1.f + expf(-gv[j]));
        float y = a[j] * rstd * gnw[t * 8 + j] * sig;
        split_bf(y, hi[j], lo[j]);
    }
    __nv_bfloat16* dst = d_y_s + (size_t)s * GK + t * 8;
    *(uint4*)(dst)        = *(uint4*)hi;
    *(uint4*)(dst + 2048) = *(uint4*)lo;
    *(uint4*)(dst + 4096) = *(uint4*)hi;
}

// ---------------------------------------------------------------------------
// Launch
// ---------------------------------------------------------------------------
extern "C" void kernel_launch(void* const* d_in, const int* in_sizes, int n_in,
                              void* d_out, int out_size)
{
    const float* hs     = (const float*)d_in[0];
    const int*   pos    = (const int*)  d_in[1];
    const float* qkv_w  = (const float*)d_in[2];
    const float* qkv_b  = (const float*)d_in[3];
    const float* qnw    = (const float*)d_in[4];
    const float* knw    = (const float*)d_in[5];
    const float* g_w    = (const float*)d_in[6];
    const float* gnw    = (const float*)d_in[7];
    const float* dens_w = (const float*)d_in[8];
    float* out = (float*)d_out;

    float *p_qkv, *p_g;
    __nv_bfloat16 *p_hs_s, *p_qkvw_s, *p_gw_s, *p_dw_s, *p_y_s;
    cudaGetSymbolAddress((void**)&p_qkv,    d_qkv);
    cudaGetSymbolAddress((void**)&p_g,      d_g);
    cudaGetSymbolAddress((void**)&p_hs_s,   d_hs_s);
    cudaGetSymbolAddress((void**)&p_qkvw_s, d_qkvw_s);
    cudaGetSymbolAddress((void**)&p_gw_s,   d_gw_s);
    cudaGetSymbolAddress((void**)&p_dw_s,   d_dw_s);
    cudaGetSymbolAddress((void**)&p_y_s,    d_y_s);

    cudaFuncSetAttribute(hmma_gemm<true>,
                         cudaFuncAttributeMaxDynamicSharedMemorySize, GEMM_SMEM);
    cudaFuncSetAttribute(hmma_gemm<false>,
                         cudaFuncAttributeMaxDynamicSharedMemorySize, GEMM_SMEM);
    cudaFuncSetAttribute(attn_hmma_kernel,
                         cudaFuncAttributeMaxDynamicSharedMemorySize, ATTN_SMEM);
    cudaFuncSetAttribute(chunk_kv_hmma,
                         cudaFuncAttributeMaxDynamicSharedMemorySize, CHUNK_SMEM);

    init_tables_kernel<<<1, 64>>>();

    split_kernel<<<(S_LEN * HID) / (256 * 8), 256>>>(hs,     p_hs_s,   1);
    split_kernel<<<(QKV_N * HID) / (256 * 8), 256>>>(qkv_w,  p_qkvw_s, 0);
    split_kernel<<<(HDTOT * HID) / (256 * 8), 256>>>(g_w,    p_gw_s,   0);
    split_kernel<<<(HDTOT * HID) / (256 * 8), 256>>>(dens_w, p_dw_s,   0);

    hmma_gemm<true><<<(S_LEN / 128) * (QKV_N / 128), 256, GEMM_SMEM>>>(
        p_hs_s, p_qkvw_s, qkv_b, p_qkv, QKV_N);
    hmma_gemm<false><<<(S_LEN / 128) * (HDTOT / 128), 256, GEMM_SMEM>>>(
        p_hs_s, p_gw_s, nullptr, p_g, HDTOT);

    normrope_kernel<<<dim3(S_LEN, NH), 128>>>(pos, qnw, knw);

    chunk_kv_hmma<<<dim3(NC, NH), 256, CHUNK_SMEM>>>();
    kv_scan_kernel<<<256, 256>>>();
    attn_hmma_kernel<<<dim3(4, NC, NH), 256, ATTN_SMEM>>>();

    gate_kernel<<<S_LEN, 256>>>(gnw);

    hmma_gemm<false><<<(S_LEN / 128) * (HDTOT / 128), 256, GEMM_SMEM>>>(
        p_y_s, p_dw_s, nullptr, out, HDTOT);
}